// round 16
// baseline (speedup 1.0000x reference)
#include <cuda_runtime.h>
#include <stdint.h>

// fftshift ∘ ifftshift on even dims (320,320): net roll = -160-160 ≡ 0 per
// dim → the whole op is the identity. Task reduces to a 104.86 MB D2D copy.
//
// CONVERGED FINAL (R9 configuration — best observed timed dur_us 35.296):
// 256-bit global accesses (ld/st.global.v8.f32, sm_100+), 2 independent
// load/store pairs per thread, 256-thread blocks, 6400 blocks × 256 × 2 == n8
// exact cover. Loads .nc + evict_first (zero reuse); stores default policy.
// Measured kernel-side at up to 7.83 TB/s combined read+write traffic
// (97.9% of 8 TB/s HBM spec; floor 26.2 µs). Timed metric is stable at
// 35.3 ± 0.5 µs across all competent variants — remaining delta over the
// kernel floor is fixed per-replay launch overhead.
//
// Probed and rejected: MLP 4/8 per thread (occupancy loss), float4 width,
// 512/1024-thread CTAs (1024 = L1tex-queue cliff at 4.9 TB/s), evict-first
// stores (neutral), cudaMemcpyAsync (slower by ~2 µs).

struct __align__(32) f32x8 { float v[8]; };

__device__ __forceinline__ f32x8 ldg256_ef(const f32x8* p) {
    f32x8 r;
    asm volatile(
        "ld.global.nc.L1::evict_first.v8.f32 {%0,%1,%2,%3,%4,%5,%6,%7}, [%8];"
        : "=f"(r.v[0]), "=f"(r.v[1]), "=f"(r.v[2]), "=f"(r.v[3]),
          "=f"(r.v[4]), "=f"(r.v[5]), "=f"(r.v[6]), "=f"(r.v[7])
        : "l"(p));
    return r;
}

__device__ __forceinline__ void stg256(f32x8* p, const f32x8& r) {
    asm volatile(
        "st.global.v8.f32 [%0], {%1,%2,%3,%4,%5,%6,%7,%8};"
        :: "l"(p),
           "f"(r.v[0]), "f"(r.v[1]), "f"(r.v[2]), "f"(r.v[3]),
           "f"(r.v[4]), "f"(r.v[5]), "f"(r.v[6]), "f"(r.v[7])
        : "memory");
}

__global__ void copy_v8x2_kernel(const f32x8* __restrict__ src,
                                 f32x8* __restrict__ dst) {
    const int stride = gridDim.x * blockDim.x;
    const int i = blockIdx.x * blockDim.x + threadIdx.x;

    f32x8 a = ldg256_ef(src + i);
    f32x8 b = ldg256_ef(src + i + stride);
    stg256(dst + i,          a);
    stg256(dst + i + stride, b);
}

// Fallback tail (not hit for this problem's exact-cover size).
__global__ void copy_f4_tail_kernel(const float4* __restrict__ src,
                                    float4* __restrict__ dst,
                                    int start, int n4) {
    int i = start + blockIdx.x * blockDim.x + threadIdx.x;
    if (i < n4) dst[i] = src[i];
}

extern "C" void kernel_launch(void* const* d_in, const int* in_sizes, int n_in,
                              void* d_out, int out_size) {
    int n4 = out_size / 4;          // float4 count: 6,553,600
    int n8 = n4 / 2;                // f32x8 count:  3,276,800

    const int threads = 256;
    const int per_block = threads * 2;          // f32x8 per block
    int blocks = n8 / per_block;                // 6400: exact cover
    if (blocks > 0) {
        copy_v8x2_kernel<<<blocks, threads>>>((const f32x8*)d_in[0],
                                              (f32x8*)d_out);
    }
    int done4 = blocks * per_block * 2;         // float4s covered
    int rem4 = n4 - done4;
    if (rem4 > 0) {
        copy_f4_tail_kernel<<<(rem4 + threads - 1) / threads, threads>>>(
            (const float4*)d_in[0], (float4*)d_out, done4, n4);
    }
}

// round 17
// speedup vs baseline: 1.0435x; 1.0435x over previous
#include <cuda_runtime.h>
#include <stdint.h>

// fftshift ∘ ifftshift on even dims (320,320): per dim the net roll is
// -ceil(320/2) + -floor(320/2) = -320 ≡ 0 → the whole op is the identity.
// Task reduces to a 104.86 MB D2D copy.
//
// CONVERGED FINAL. 256-bit global accesses (ld/st.global.v8.f32, sm_100+),
// 2 independent load/store pairs per thread, 256-thread blocks,
// 6400 blocks × 256 × 2 == n8 exact cover. Loads .nc + evict_first (zero
// reuse); stores default policy.
//
// Roofline: 209.7 MB combined traffic; best kernel obs 26.78 µs = 7.83 TB/s
// = 97.9% of 8 TB/s HBM spec (floor 26.2 µs). Timed dur_us = kernel +
// ~8.5 µs fixed graph-replay overhead, noise ±0.8 µs. Replications of this
// exact config: 35.30 / 36.86 µs. Probed and rejected over 15 rounds:
// MLP 4/8 (occupancy loss), float4 width, 512-thread (equal), 1024-thread
// CTAs (L1tex-queue cliff, 4.9 TB/s), evict-first stores (neutral),
// cudaMemcpyAsync (~2 µs slower). No remaining lever exceeds noise.

struct __align__(32) f32x8 { float v[8]; };

__device__ __forceinline__ f32x8 ldg256_ef(const f32x8* p) {
    f32x8 r;
    asm volatile(
        "ld.global.nc.L1::evict_first.v8.f32 {%0,%1,%2,%3,%4,%5,%6,%7}, [%8];"
        : "=f"(r.v[0]), "=f"(r.v[1]), "=f"(r.v[2]), "=f"(r.v[3]),
          "=f"(r.v[4]), "=f"(r.v[5]), "=f"(r.v[6]), "=f"(r.v[7])
        : "l"(p));
    return r;
}

__device__ __forceinline__ void stg256(f32x8* p, const f32x8& r) {
    asm volatile(
        "st.global.v8.f32 [%0], {%1,%2,%3,%4,%5,%6,%7,%8};"
        :: "l"(p),
           "f"(r.v[0]), "f"(r.v[1]), "f"(r.v[2]), "f"(r.v[3]),
           "f"(r.v[4]), "f"(r.v[5]), "f"(r.v[6]), "f"(r.v[7])
        : "memory");
}

__global__ void copy_v8x2_kernel(const f32x8* __restrict__ src,
                                 f32x8* __restrict__ dst) {
    const int stride = gridDim.x * blockDim.x;
    const int i = blockIdx.x * blockDim.x + threadIdx.x;

    f32x8 a = ldg256_ef(src + i);
    f32x8 b = ldg256_ef(src + i + stride);
    stg256(dst + i,          a);
    stg256(dst + i + stride, b);
}

// Fallback tail (not hit for this problem's exact-cover size).
__global__ void copy_f4_tail_kernel(const float4* __restrict__ src,
                                    float4* __restrict__ dst,
                                    int start, int n4) {
    int i = start + blockIdx.x * blockDim.x + threadIdx.x;
    if (i < n4) dst[i] = src[i];
}

extern "C" void kernel_launch(void* const* d_in, const int* in_sizes, int n_in,
                              void* d_out, int out_size) {
    int n4 = out_size / 4;          // float4 count: 6,553,600
    int n8 = n4 / 2;                // f32x8 count:  3,276,800

    const int threads = 256;
    const int per_block = threads * 2;          // f32x8 per block
    int blocks = n8 / per_block;                // 6400: exact cover
    if (blocks > 0) {
        copy_v8x2_kernel<<<blocks, threads>>>((const f32x8*)d_in[0],
                                              (f32x8*)d_out);
    }
    int done4 = blocks * per_block * 2;         // float4s covered
    int rem4 = n4 - done4;
    if (rem4 > 0) {
        copy_f4_tail_kernel<<<(rem4 + threads - 1) / threads, threads>>>(
            (const float4*)d_in[0], (float4*)d_out, done4, n4);
    }
}